// round 7
// baseline (speedup 1.0000x reference)
#include <cuda_runtime.h>
#include <cstdint>

#define N_NODES 25000
#define N_EDGES 320000
#define F       64
#define NHEADS  5
#define NRELS   20
#define NBASES  10
#define OUTC    320
#define PCOLS   200          // GEMM P-columns (compact): 100 s + 100 d
#define PSTRIDE 320          // padded per-node P row: 20 rels * 16
#define TOTC    584          // 64 z + 320 self_z + 200 P
#define CHUNK   32

// ---------------- static device scratch ------------------------------------
__device__ float    g_z [N_NODES * F];          // 6.4 MB
__device__ float    g_W2[64 * PCOLS];
__device__ float    g_P [N_NODES * PSTRIDE];    // 32 MB padded
__device__ int      g_cnt [N_NODES];            // zero at load; self-restored by scan3
__device__ int      g_scan[N_NODES];
__device__ int      g_bsum[32];
__device__ int      g_cur [N_NODES];
__device__ unsigned g_srcrt[N_EDGES];           // src | rel<<16, sorted by dst
__device__ int      g_dstS [N_EDGES];           // dst, sorted

// ---------------- f32x2 helpers ---------------------------------------------
__device__ __forceinline__ unsigned long long pack2(float x) {
    unsigned long long r; asm("mov.b64 %0, {%1, %1};" : "=l"(r) : "f"(x)); return r;
}
__device__ __forceinline__ void fma2(unsigned long long& d,
                                     unsigned long long a, unsigned long long b) {
    asm("fma.rn.f32x2 %0, %1, %2, %0;" : "+l"(d) : "l"(a), "l"(b));
}
__device__ __forceinline__ void unpack2(unsigned long long v, float& lo, float& hi) {
    asm("mov.b64 {%0, %1}, %2;" : "=f"(lo), "=f"(hi) : "l"(v));
}

// ---------------------------------------------------------------------------
// K1: attention-weight composition.  One block per relation.
// ---------------------------------------------------------------------------
__global__ void __launch_bounds__(320) attn_comp_kernel(const float* __restrict__ aw,
                                                        const float* __restrict__ w_comp,
                                                        const float* __restrict__ fc_w)
{
    __shared__ float afc[128 * NHEADS];
    const int r = blockIdx.x, tid = threadIdx.x;

    if (tid < 128) {
        float acc[NHEADS] = {};
#pragma unroll
        for (int b = 0; b < NBASES; b++) {
            float wc = w_comp[r * NBASES + b];
#pragma unroll
            for (int h = 0; h < NHEADS; h++)
                acc[h] += wc * aw[(b * 128 + tid) * NHEADS + h];
        }
#pragma unroll
        for (int h = 0; h < NHEADS; h++) afc[tid * NHEADS + h] = acc[h];
    }
    __syncthreads();

    for (int o = tid; o < 640; o += 320) {
        int k = o / 10, c2 = o % 10, h = c2 % 5;
        const float* af = afc + (c2 >= 5 ? 64 * NHEADS : 0) + h;
        float sum = 0.f;
#pragma unroll
        for (int f = 0; f < 64; f++) sum += fc_w[k * 64 + f] * af[f * NHEADS];
        g_W2[k * PCOLS + (c2 >= 5 ? 100 : 0) + r * 5 + h] = sum;
    }
}

// ---------------------------------------------------------------------------
// Sort chain: hist -> scan1 -> scan3(+cnt reset) -> scatter
// ---------------------------------------------------------------------------
__global__ void hist_kernel(const int* __restrict__ dst)
{
    int e = blockIdx.x * blockDim.x + threadIdx.x;
    if (e < N_EDGES) atomicAdd(&g_cnt[dst[e]], 1);
}

__global__ void __launch_bounds__(1024) scan1_kernel()
{
    __shared__ int wsum[32];
    const int tid = threadIdx.x, lane = tid & 31, wid = tid >> 5;
    const int idx = blockIdx.x * 1024 + tid;
    int v = (idx < N_NODES) ? g_cnt[idx] : 0;
    int x = v;
#pragma unroll
    for (int d = 1; d < 32; d <<= 1) {
        int y = __shfl_up_sync(0xffffffffu, x, d);
        if (lane >= d) x += y;
    }
    if (lane == 31) wsum[wid] = x;
    __syncthreads();
    if (tid < 32) {
        int w = wsum[tid];
#pragma unroll
        for (int d = 1; d < 32; d <<= 1) {
            int y = __shfl_up_sync(0xffffffffu, w, d);
            if (tid >= d) w += y;
        }
        wsum[tid] = w;
    }
    __syncthreads();
    int incl = x + (wid > 0 ? wsum[wid - 1] : 0);
    if (idx < N_NODES) g_scan[idx] = incl;
    if (tid == 1023)   g_bsum[blockIdx.x] = incl;
}

__global__ void __launch_bounds__(1024) scan3_kernel()
{
    __shared__ int s_pre;
    const int tid = threadIdx.x;
    if (tid < 32) {
        int v = (tid < blockIdx.x) ? g_bsum[tid] : 0;
#pragma unroll
        for (int d = 16; d > 0; d >>= 1) v += __shfl_xor_sync(0xffffffffu, v, d);
        if (tid == 0) s_pre = v;
    }
    __syncthreads();
    int idx = blockIdx.x * 1024 + tid;
    if (idx < N_NODES) {
        int c = g_cnt[idx];
        g_cur[idx] = g_scan[idx] + s_pre - c;   // exclusive start = scatter cursor
        g_cnt[idx] = 0;                         // self-restore for next replay
    }
}

__global__ void scatter_kernel(const int* __restrict__ dst,
                               const int* __restrict__ src,
                               const int* __restrict__ et)
{
    int e = blockIdx.x * blockDim.x + threadIdx.x;
    if (e < N_EDGES) {
        int d = dst[e];
        int pos = atomicAdd(&g_cur[d], 1);
        g_srcrt[pos] = (unsigned)src[e] | ((unsigned)et[e] << 16);
        g_dstS[pos]  = d;
    }
}

// ---------------------------------------------------------------------------
// proj: fused projection GEMM, packed f32x2, occupancy-tuned.
// Tile 64 rows x 128 cols, 256 threads, 4x8 microtile (16 f32x2 accs).
// cols 0..63 -> g_z, 64..383 -> d_out, 384..583 -> g_P (padded remap).
// ---------------------------------------------------------------------------
__global__ void __launch_bounds__(256) proj_kernel(const float* __restrict__ feat,
                                                   const float* __restrict__ fc_w,
                                                   const float* __restrict__ self_fc_w,
                                                   float* __restrict__ out)
{
    __shared__ float As[64][65];    // ~16.6 KB
    __shared__ float Bs[64][132];   // ~33.8 KB

    const int tid = threadIdx.x;
    const int m0  = blockIdx.x * 64;
    const int c0  = blockIdx.y * 128;

    // A tile: 64 rows x 16 float4
#pragma unroll
    for (int i = 0; i < 4; i++) {
        int v = tid + i * 256;
        int row = v >> 4, k4 = (v & 15) * 4;
        int node = m0 + row;
        float4 a = make_float4(0.f, 0.f, 0.f, 0.f);
        if (node < N_NODES) a = *(const float4*)(feat + node * F + k4);
        As[row][k4 + 0] = a.x; As[row][k4 + 1] = a.y;
        As[row][k4 + 2] = a.z; As[row][k4 + 3] = a.w;
    }
    // B tile: 64 k-rows x 32 float4
#pragma unroll
    for (int i = 0; i < 8; i++) {
        int v = tid + i * 256;
        int k = v >> 5, c4 = (v & 31) * 4;
        int gc = c0 + c4;
        float4 b = make_float4(0.f, 0.f, 0.f, 0.f);
        if (gc < 64)        b = *(const float4*)(fc_w + k * 64 + gc);
        else if (gc < 384)  b = *(const float4*)(self_fc_w + k * 320 + (gc - 64));
        else if (gc < TOTC) b = *(const float4*)(g_W2 + k * PCOLS + (gc - 384));
        *(float4*)&Bs[k][c4] = b;
    }
    __syncthreads();

    const int tx = tid & 15, ty = tid >> 4;     // cols 8*tx.., rows 4*ty..
    unsigned long long acc[4][4];
#pragma unroll
    for (int i = 0; i < 4; i++)
#pragma unroll
        for (int j = 0; j < 4; j++) acc[i][j] = 0ull;

#pragma unroll 8
    for (int k = 0; k < 64; k++) {
        unsigned long long a2[4];
#pragma unroll
        for (int i = 0; i < 4; i++) a2[i] = pack2(As[4 * ty + i][k]);
        float4 b0 = *(const float4*)&Bs[k][8 * tx];
        float4 b1 = *(const float4*)&Bs[k][8 * tx + 4];
        unsigned long long b2[4];
        b2[0] = *(const unsigned long long*)&b0.x;
        b2[1] = *(const unsigned long long*)&b0.z;
        b2[2] = *(const unsigned long long*)&b1.x;
        b2[3] = *(const unsigned long long*)&b1.z;
#pragma unroll
        for (int i = 0; i < 4; i++)
#pragma unroll
            for (int j = 0; j < 4; j++) fma2(acc[i][j], a2[i], b2[j]);
    }

#pragma unroll
    for (int i = 0; i < 4; i++) {
        int node = m0 + 4 * ty + i;
        if (node >= N_NODES) continue;
#pragma unroll
        for (int j = 0; j < 4; j++) {
            int gc = c0 + 8 * tx + 2 * j;
            if (gc < 64) {
                *(unsigned long long*)(g_z + node * F + gc) = acc[i][j];
            } else if (gc < 384) {
                *(unsigned long long*)(out + node * OUTC + (gc - 64)) = acc[i][j];
            } else if (gc < TOTC) {
                float lo, hi;
                unpack2(acc[i][j], lo, hi);
#pragma unroll
                for (int t = 0; t < 2; t++) {
                    int ix = gc - 384 + t;
                    if (ix >= PCOLS) continue;
                    int part = (ix >= 100) ? 8 : 0;
                    int pix  = (ix >= 100) ? ix - 100 : ix;
                    int rr = pix / 5, hh = pix % 5;   // mul-high, cheap
                    g_P[node * PSTRIDE + rr * 16 + part + hh] = t ? hi : lo;
                }
            }
        }
    }
}

// ---------------------------------------------------------------------------
// gather: edge-parallel aggregation over dst-sorted edges (r6, padded P).
// ---------------------------------------------------------------------------
__global__ void __launch_bounds__(256) gather_kernel(float* __restrict__ out)
{
    __shared__ float stage[8][328];
    const int w = threadIdx.x >> 5, lane = threadIdx.x & 31;
    const int gw = blockIdx.x * 8 + w;
    const int e0 = gw * CHUNK;
    if (e0 >= N_EDGES) return;
    const int e1 = min(e0 + CHUNK, N_EDGES);

    float acc[10];
#pragma unroll
    for (int q = 0; q < 10; q++) acc[q] = 0.f;

    int      d_n = g_dstS[e0];
    unsigned pk  = g_srcrt[e0];
    int s_n = pk & 0xFFFFu, r_n = pk >> 16;
    float2 zs_n = *(const float2*)(g_z + s_n * F + 2 * lane);
    const float* pp = g_P + s_n * PSTRIDE + r_n * 16;
    const float* qq = g_P + d_n * PSTRIDE + r_n * 16 + 8;
    float4 ps4_n = *(const float4*)pp;  float ps1_n = pp[4];
    float4 pd4_n = *(const float4*)qq;  float pd1_n = qq[4];
    int d_cur = d_n;

    for (int i = e0; i < e1; i++) {
        const int    d_c  = d_n;
        const float2 zs   = zs_n;
        const float4 ps4  = ps4_n, pd4 = pd4_n;
        const float  ps1  = ps1_n, pd1 = pd1_n;

        if (i + 1 < e1) {
            d_n = g_dstS[i + 1];
            pk  = g_srcrt[i + 1];
            int s2 = pk & 0xFFFFu, r2 = pk >> 16;
            zs_n = *(const float2*)(g_z + s2 * F + 2 * lane);
            const float* p2 = g_P + s2 * PSTRIDE + r2 * 16;
            const float* p3 = g_P + d_n * PSTRIDE + r2 * 16 + 8;
            ps4_n = *(const float4*)p2;  ps1_n = p2[4];
            pd4_n = *(const float4*)p3;  pd1_n = p3[4];
        }

        if (d_c != d_cur) {   // warp-uniform branch
#pragma unroll
            for (int h = 0; h < NHEADS; h++)
                *(float2*)&stage[w][h * F + 2 * lane] = make_float2(acc[2 * h], acc[2 * h + 1]);
            __syncwarp();
            float* ob = out + (long)d_cur * OUTC;
#pragma unroll
            for (int t = 0; t < 3; t++) {
                int cc = lane + 32 * t;
                if (cc < 80) {
                    float4 v = *(const float4*)&stage[w][cc * 4];
                    asm volatile("red.global.add.v4.f32 [%0], {%1, %2, %3, %4};"
                                 :: "l"(ob + 4 * cc), "f"(v.x), "f"(v.y), "f"(v.z), "f"(v.w)
                                 : "memory");
                }
            }
            __syncwarp();
#pragma unroll
            for (int q = 0; q < 10; q++) acc[q] = 0.f;
            d_cur = d_c;
        }

        float a0 = ps4.x + pd4.x;  a0 = a0 > 0.f ? a0 : 0.01f * a0;
        float a1 = ps4.y + pd4.y;  a1 = a1 > 0.f ? a1 : 0.01f * a1;
        float a2 = ps4.z + pd4.z;  a2 = a2 > 0.f ? a2 : 0.01f * a2;
        float a3 = ps4.w + pd4.w;  a3 = a3 > 0.f ? a3 : 0.01f * a3;
        float a4 = ps1   + pd1;    a4 = a4 > 0.f ? a4 : 0.01f * a4;
        acc[0] += a0 * zs.x;  acc[1] += a0 * zs.y;
        acc[2] += a1 * zs.x;  acc[3] += a1 * zs.y;
        acc[4] += a2 * zs.x;  acc[5] += a2 * zs.y;
        acc[6] += a3 * zs.x;  acc[7] += a3 * zs.y;
        acc[8] += a4 * zs.x;  acc[9] += a4 * zs.y;
    }

    // final flush
#pragma unroll
    for (int h = 0; h < NHEADS; h++)
        *(float2*)&stage[w][h * F + 2 * lane] = make_float2(acc[2 * h], acc[2 * h + 1]);
    __syncwarp();
    float* ob = out + (long)d_cur * OUTC;
#pragma unroll
    for (int t = 0; t < 3; t++) {
        int cc = lane + 32 * t;
        if (cc < 80) {
            float4 v = *(const float4*)&stage[w][cc * 4];
            asm volatile("red.global.add.v4.f32 [%0], {%1, %2, %3, %4};"
                         :: "l"(ob + 4 * cc), "f"(v.x), "f"(v.y), "f"(v.z), "f"(v.w)
                         : "memory");
        }
    }
}

// ---------------------------------------------------------------------------
extern "C" void kernel_launch(void* const* d_in, const int* in_sizes, int n_in,
                              void* d_out, int out_size)
{
    const float* feat      = (const float*)d_in[0];
    const int*   src       = (const int*)  d_in[1];
    const int*   dst       = (const int*)  d_in[2];
    const int*   etype     = (const int*)  d_in[3];
    const float* fc_w      = (const float*)d_in[4];
    const float* self_fc_w = (const float*)d_in[5];
    const float* aw        = (const float*)d_in[6];
    const float* w_comp    = (const float*)d_in[7];
    float* out = (float*)d_out;

    const int NB = (N_NODES + 1023) / 1024;   // 25

    attn_comp_kernel<<<NRELS, 320>>>(aw, w_comp, fc_w);                 // 1
    hist_kernel<<<(N_EDGES + 255) / 256, 256>>>(dst);                   // 2
    scan1_kernel<<<NB, 1024>>>();                                       // 3
    proj_kernel<<<dim3((N_NODES + 63) / 64, 5), 256>>>(feat, fc_w, self_fc_w, out); // 4 (profiled)
    scan3_kernel<<<NB, 1024>>>();                                       // 5
    scatter_kernel<<<(N_EDGES + 255) / 256, 256>>>(dst, src, etype);    // 6
    gather_kernel<<<(N_EDGES / CHUNK + 7) / 8, 256>>>(out);             // 7
}

// round 8
// speedup vs baseline: 1.2343x; 1.2343x over previous
#include <cuda_runtime.h>
#include <cstdint>

#define N_NODES 25000
#define N_EDGES 320000
#define F       64
#define NHEADS  5
#define NRELS   20
#define NBASES  10
#define OUTC    320
#define PCOLS   200          // GEMM P-columns (compact): 100 s + 100 d
#define PSTRIDE 320          // padded per-node P row: 20 rels * 16
#define TOTC    584          // 64 z + 320 self_z + 200 P
#define CHUNK   32

// ---------------- static device scratch ------------------------------------
__device__ float    g_z [N_NODES * F];          // 6.4 MB
__device__ float    g_W2[64 * PCOLS];
__device__ float    g_P [N_NODES * PSTRIDE];    // 32 MB padded
__device__ int      g_cnt [N_NODES];            // zero at load; self-restored by scan3
__device__ int      g_scan[N_NODES];
__device__ int      g_bsum[32];
__device__ int      g_cur [N_NODES];
__device__ unsigned g_srcrt[N_EDGES];           // src | rel<<16, sorted by dst
__device__ int      g_dstS [N_EDGES];           // dst, sorted

// ---------------- tf32 helpers ----------------------------------------------
__device__ __forceinline__ uint32_t f2tf32(float x) {
    uint32_t u;
    asm("cvt.rn.tf32.f32 %0, %1;" : "=r"(u) : "f"(x));
    return u;
}
// split x into (hi, lo) tf32 pair
__device__ __forceinline__ void tf32_split(float x, uint32_t& hi, uint32_t& lo) {
    hi = f2tf32(x);
    float r = x - __uint_as_float(hi);
    lo = f2tf32(r);
}
__device__ __forceinline__ void mma_tf32(float* d, const uint32_t* a, const uint32_t* b) {
    asm volatile("mma.sync.aligned.m16n8k8.row.col.f32.tf32.tf32.f32 "
                 "{%0,%1,%2,%3}, {%4,%5,%6,%7}, {%8,%9}, {%0,%1,%2,%3};"
                 : "+f"(d[0]), "+f"(d[1]), "+f"(d[2]), "+f"(d[3])
                 : "r"(a[0]), "r"(a[1]), "r"(a[2]), "r"(a[3]), "r"(b[0]), "r"(b[1]));
}

// ---------------------------------------------------------------------------
// K1: attention-weight composition.  One block per relation.
// ---------------------------------------------------------------------------
__global__ void __launch_bounds__(320) attn_comp_kernel(const float* __restrict__ aw,
                                                        const float* __restrict__ w_comp,
                                                        const float* __restrict__ fc_w)
{
    __shared__ float afc[128 * NHEADS];
    const int r = blockIdx.x, tid = threadIdx.x;

    if (tid < 128) {
        float acc[NHEADS] = {};
#pragma unroll
        for (int b = 0; b < NBASES; b++) {
            float wc = w_comp[r * NBASES + b];
#pragma unroll
            for (int h = 0; h < NHEADS; h++)
                acc[h] += wc * aw[(b * 128 + tid) * NHEADS + h];
        }
#pragma unroll
        for (int h = 0; h < NHEADS; h++) afc[tid * NHEADS + h] = acc[h];
    }
    __syncthreads();

    for (int o = tid; o < 640; o += 320) {
        int k = o / 10, c2 = o % 10, h = c2 % 5;
        const float* af = afc + (c2 >= 5 ? 64 * NHEADS : 0) + h;
        float sum = 0.f;
#pragma unroll
        for (int f = 0; f < 64; f++) sum += fc_w[k * 64 + f] * af[f * NHEADS];
        g_W2[k * PCOLS + (c2 >= 5 ? 100 : 0) + r * 5 + h] = sum;
    }
}

// ---------------------------------------------------------------------------
// Sort chain: hist -> scan1 -> scan3(+cnt reset) -> scatter
// ---------------------------------------------------------------------------
__global__ void hist_kernel(const int* __restrict__ dst)
{
    int e = blockIdx.x * blockDim.x + threadIdx.x;
    if (e < N_EDGES) atomicAdd(&g_cnt[dst[e]], 1);
}

__global__ void __launch_bounds__(1024) scan1_kernel()
{
    __shared__ int wsum[32];
    const int tid = threadIdx.x, lane = tid & 31, wid = tid >> 5;
    const int idx = blockIdx.x * 1024 + tid;
    int v = (idx < N_NODES) ? g_cnt[idx] : 0;
    int x = v;
#pragma unroll
    for (int d = 1; d < 32; d <<= 1) {
        int y = __shfl_up_sync(0xffffffffu, x, d);
        if (lane >= d) x += y;
    }
    if (lane == 31) wsum[wid] = x;
    __syncthreads();
    if (tid < 32) {
        int w = wsum[tid];
#pragma unroll
        for (int d = 1; d < 32; d <<= 1) {
            int y = __shfl_up_sync(0xffffffffu, w, d);
            if (tid >= d) w += y;
        }
        wsum[tid] = w;
    }
    __syncthreads();
    int incl = x + (wid > 0 ? wsum[wid - 1] : 0);
    if (idx < N_NODES) g_scan[idx] = incl;
    if (tid == 1023)   g_bsum[blockIdx.x] = incl;
}

__global__ void __launch_bounds__(1024) scan3_kernel()
{
    __shared__ int s_pre;
    const int tid = threadIdx.x;
    if (tid < 32) {
        int v = (tid < blockIdx.x) ? g_bsum[tid] : 0;
#pragma unroll
        for (int d = 16; d > 0; d >>= 1) v += __shfl_xor_sync(0xffffffffu, v, d);
        if (tid == 0) s_pre = v;
    }
    __syncthreads();
    int idx = blockIdx.x * 1024 + tid;
    if (idx < N_NODES) {
        int c = g_cnt[idx];
        g_cur[idx] = g_scan[idx] + s_pre - c;
        g_cnt[idx] = 0;                        // self-restore for next replay
    }
}

__global__ void scatter_kernel(const int* __restrict__ dst,
                               const int* __restrict__ src,
                               const int* __restrict__ et)
{
    int e = blockIdx.x * blockDim.x + threadIdx.x;
    if (e < N_EDGES) {
        int d = dst[e];
        int pos = atomicAdd(&g_cur[d], 1);
        g_srcrt[pos] = (unsigned)src[e] | ((unsigned)et[e] << 16);
        g_dstS[pos]  = d;
    }
}

// ---------------------------------------------------------------------------
// proj_mma: tensor-core (mma.sync tf32, 3x-split) fused projection GEMM.
// feat[25000x64] @ [fc_w | self_fc_w | W2] -> g_z | d_out | g_P.
// Block: 128 rows x 64 cols, 256 thr (8 warps, warp = m16 x n64).
// Dynamic smem: AsHi/AsLo [128][68], BsHi/BsLo [64][72]  (~104 KB).
// ---------------------------------------------------------------------------
#define APAD 68
#define BPAD 72
#define PROJ_SMEM ((128 * APAD * 2 + 64 * BPAD * 2) * 4)

__global__ void __launch_bounds__(256) proj_mma_kernel(const float* __restrict__ feat,
                                                       const float* __restrict__ fc_w,
                                                       const float* __restrict__ self_fc_w,
                                                       float* __restrict__ out)
{
    extern __shared__ uint32_t smem[];
    uint32_t* AsHi = smem;
    uint32_t* AsLo = AsHi + 128 * APAD;
    uint32_t* BsHi = AsLo + 128 * APAD;
    uint32_t* BsLo = BsHi + 64 * BPAD;

    const int tid = threadIdx.x;
    const int m0  = blockIdx.x * 128;
    const int c0  = blockIdx.y * 64;

    // ---- load + split A tile (128 x 64)
#pragma unroll
    for (int i = 0; i < 8; i++) {
        int v = tid + i * 256;                 // 0..2047 float4 slots
        int row = v >> 4, c4 = (v & 15) * 4;
        int node = m0 + row;
        float4 a = make_float4(0.f, 0.f, 0.f, 0.f);
        if (node < N_NODES) a = *(const float4*)(feat + node * F + c4);
        uint32_t* hp = AsHi + row * APAD + c4;
        uint32_t* lp = AsLo + row * APAD + c4;
        tf32_split(a.x, hp[0], lp[0]);
        tf32_split(a.y, hp[1], lp[1]);
        tf32_split(a.z, hp[2], lp[2]);
        tf32_split(a.w, hp[3], lp[3]);
    }
    // ---- load + split B tile (64 k x 64 n)
#pragma unroll
    for (int i = 0; i < 4; i++) {
        int v = tid + i * 256;                 // 0..1023 float4 slots
        int k = v >> 4, n4 = (v & 15) * 4;
        int gc = c0 + n4;
        float4 b = make_float4(0.f, 0.f, 0.f, 0.f);
        if (gc < 64)        b = *(const float4*)(fc_w + k * 64 + gc);
        else if (gc < 384)  b = *(const float4*)(self_fc_w + k * 320 + (gc - 64));
        else if (gc < TOTC) b = *(const float4*)(g_W2 + k * PCOLS + (gc - 384));
        uint32_t* hp = BsHi + k * BPAD + n4;
        uint32_t* lp = BsLo + k * BPAD + n4;
        tf32_split(b.x, hp[0], lp[0]);
        tf32_split(b.y, hp[1], lp[1]);
        tf32_split(b.z, hp[2], lp[2]);
        tf32_split(b.w, hp[3], lp[3]);
    }
    __syncthreads();

    const int wid  = tid >> 5;
    const int lane = tid & 31;
    const int gid  = lane >> 2;       // 0..7
    const int tig  = lane & 3;        // 0..3

    float d[8][4];
#pragma unroll
    for (int j = 0; j < 8; j++)
#pragma unroll
        for (int q = 0; q < 4; q++) d[j][q] = 0.f;

    const uint32_t* ahp = AsHi + (16 * wid + gid) * APAD + tig;
    const uint32_t* alp = AsLo + (16 * wid + gid) * APAD + tig;
    const uint32_t* bhp = BsHi + tig * BPAD + gid;
    const uint32_t* blp = BsLo + tig * BPAD + gid;

#pragma unroll
    for (int ks = 0; ks < 8; ks++) {
        uint32_t ah[4], al[4];
        ah[0] = ahp[ks * 8];
        ah[1] = ahp[8 * APAD + ks * 8];
        ah[2] = ahp[ks * 8 + 4];
        ah[3] = ahp[8 * APAD + ks * 8 + 4];
        al[0] = alp[ks * 8];
        al[1] = alp[8 * APAD + ks * 8];
        al[2] = alp[ks * 8 + 4];
        al[3] = alp[8 * APAD + ks * 8 + 4];
#pragma unroll
        for (int j = 0; j < 8; j++) {
            uint32_t bh[2], bl[2];
            bh[0] = bhp[ks * 8 * BPAD + 8 * j];
            bh[1] = bhp[(ks * 8 + 4) * BPAD + 8 * j];
            bl[0] = blp[ks * 8 * BPAD + 8 * j];
            bl[1] = blp[(ks * 8 + 4) * BPAD + 8 * j];
            mma_tf32(d[j], ah, bh);
            mma_tf32(d[j], al, bh);
            mma_tf32(d[j], ah, bl);
        }
    }

    // ---- epilogue: route to g_z / out / g_P
    const int r0 = m0 + 16 * wid + gid;
    const int cb = tig * 2;
#pragma unroll
    for (int j = 0; j < 8; j++) {
        int gc = c0 + 8 * j + cb;
        if (gc >= TOTC) continue;
#pragma unroll
        for (int half = 0; half < 2; half++) {
            int node = r0 + 8 * half;
            if (node >= N_NODES) continue;
            float x = d[j][2 * half], y = d[j][2 * half + 1];
            if (gc < 64) {
                *(float2*)(g_z + node * F + gc) = make_float2(x, y);
            } else if (gc < 384) {
                *(float2*)(out + node * OUTC + (gc - 64)) = make_float2(x, y);
            } else {
#pragma unroll
                for (int t = 0; t < 2; t++) {
                    int ix = gc - 384 + t;
                    int part = (ix >= 100) ? 8 : 0;
                    int pix  = (ix >= 100) ? ix - 100 : ix;
                    int rr = pix / 5, hh = pix % 5;
                    g_P[node * PSTRIDE + rr * 16 + part + hh] = t ? y : x;
                }
            }
        }
    }
}

// ---------------------------------------------------------------------------
// gather: edge-parallel aggregation over dst-sorted edges (r7, padded P).
// ---------------------------------------------------------------------------
__global__ void __launch_bounds__(256) gather_kernel(float* __restrict__ out)
{
    __shared__ float stage[8][328];
    const int w = threadIdx.x >> 5, lane = threadIdx.x & 31;
    const int gw = blockIdx.x * 8 + w;
    const int e0 = gw * CHUNK;
    if (e0 >= N_EDGES) return;
    const int e1 = min(e0 + CHUNK, N_EDGES);

    float acc[10];
#pragma unroll
    for (int q = 0; q < 10; q++) acc[q] = 0.f;

    int      d_n = g_dstS[e0];
    unsigned pk  = g_srcrt[e0];
    int s_n = pk & 0xFFFFu, r_n = pk >> 16;
    float2 zs_n = *(const float2*)(g_z + s_n * F + 2 * lane);
    const float* pp = g_P + s_n * PSTRIDE + r_n * 16;
    const float* qq = g_P + d_n * PSTRIDE + r_n * 16 + 8;
    float4 ps4_n = *(const float4*)pp;  float ps1_n = pp[4];
    float4 pd4_n = *(const float4*)qq;  float pd1_n = qq[4];
    int d_cur = d_n;

    for (int i = e0; i < e1; i++) {
        const int    d_c  = d_n;
        const float2 zs   = zs_n;
        const float4 ps4  = ps4_n, pd4 = pd4_n;
        const float  ps1  = ps1_n, pd1 = pd1_n;

        if (i + 1 < e1) {
            d_n = g_dstS[i + 1];
            pk  = g_srcrt[i + 1];
            int s2 = pk & 0xFFFFu, r2 = pk >> 16;
            zs_n = *(const float2*)(g_z + s2 * F + 2 * lane);
            const float* p2 = g_P + s2 * PSTRIDE + r2 * 16;
            const float* p3 = g_P + d_n * PSTRIDE + r2 * 16 + 8;
            ps4_n = *(const float4*)p2;  ps1_n = p2[4];
            pd4_n = *(const float4*)p3;  pd1_n = p3[4];
        }

        if (d_c != d_cur) {   // warp-uniform branch
#pragma unroll
            for (int h = 0; h < NHEADS; h++)
                *(float2*)&stage[w][h * F + 2 * lane] = make_float2(acc[2 * h], acc[2 * h + 1]);
            __syncwarp();
            float* ob = out + (long)d_cur * OUTC;
#pragma unroll
            for (int t = 0; t < 3; t++) {
                int cc = lane + 32 * t;
                if (cc < 80) {
                    float4 v = *(const float4*)&stage[w][cc * 4];
                    asm volatile("red.global.add.v4.f32 [%0], {%1, %2, %3, %4};"
                                 :: "l"(ob + 4 * cc), "f"(v.x), "f"(v.y), "f"(v.z), "f"(v.w)
                                 : "memory");
                }
            }
            __syncwarp();
#pragma unroll
            for (int q = 0; q < 10; q++) acc[q] = 0.f;
            d_cur = d_c;
        }

        float a0 = ps4.x + pd4.x;  a0 = a0 > 0.f ? a0 : 0.01f * a0;
        float a1 = ps4.y + pd4.y;  a1 = a1 > 0.f ? a1 : 0.01f * a1;
        float a2 = ps4.z + pd4.z;  a2 = a2 > 0.f ? a2 : 0.01f * a2;
        float a3 = ps4.w + pd4.w;  a3 = a3 > 0.f ? a3 : 0.01f * a3;
        float a4 = ps1   + pd1;    a4 = a4 > 0.f ? a4 : 0.01f * a4;
        acc[0] += a0 * zs.x;  acc[1] += a0 * zs.y;
        acc[2] += a1 * zs.x;  acc[3] += a1 * zs.y;
        acc[4] += a2 * zs.x;  acc[5] += a2 * zs.y;
        acc[6] += a3 * zs.x;  acc[7] += a3 * zs.y;
        acc[8] += a4 * zs.x;  acc[9] += a4 * zs.y;
    }

    // final flush
#pragma unroll
    for (int h = 0; h < NHEADS; h++)
        *(float2*)&stage[w][h * F + 2 * lane] = make_float2(acc[2 * h], acc[2 * h + 1]);
    __syncwarp();
    float* ob = out + (long)d_cur * OUTC;
#pragma unroll
    for (int t = 0; t < 3; t++) {
        int cc = lane + 32 * t;
        if (cc < 80) {
            float4 v = *(const float4*)&stage[w][cc * 4];
            asm volatile("red.global.add.v4.f32 [%0], {%1, %2, %3, %4};"
                         :: "l"(ob + 4 * cc), "f"(v.x), "f"(v.y), "f"(v.z), "f"(v.w)
                         : "memory");
        }
    }
}

// ---------------------------------------------------------------------------
extern "C" void kernel_launch(void* const* d_in, const int* in_sizes, int n_in,
                              void* d_out, int out_size)
{
    const float* feat      = (const float*)d_in[0];
    const int*   src       = (const int*)  d_in[1];
    const int*   dst       = (const int*)  d_in[2];
    const int*   etype     = (const int*)  d_in[3];
    const float* fc_w      = (const float*)d_in[4];
    const float* self_fc_w = (const float*)d_in[5];
    const float* aw        = (const float*)d_in[6];
    const float* w_comp    = (const float*)d_in[7];
    float* out = (float*)d_out;

    const int NB = (N_NODES + 1023) / 1024;   // 25

    cudaFuncSetAttribute(proj_mma_kernel,
                         cudaFuncAttributeMaxDynamicSharedMemorySize, PROJ_SMEM);

    attn_comp_kernel<<<NRELS, 320>>>(aw, w_comp, fc_w);                 // 1
    hist_kernel<<<(N_EDGES + 255) / 256, 256>>>(dst);                   // 2
    scan1_kernel<<<NB, 1024>>>();                                       // 3
    proj_mma_kernel<<<dim3((N_NODES + 127) / 128, 10), 256, PROJ_SMEM>>>(feat, fc_w, self_fc_w, out); // 4 (profiled)
    scan3_kernel<<<NB, 1024>>>();                                       // 5
    scatter_kernel<<<(N_EDGES + 255) / 256, 256>>>(dst, src, etype);    // 6
    gather_kernel<<<(N_EDGES / CHUNK + 7) / 8, 256>>>(out);             // 7
}